// round 12
// baseline (speedup 1.0000x reference)
#include <cuda_runtime.h>
#include <cuda_fp16.h>
#include <math.h>
#include <stdint.h>

#define Bdim 32
#define Sdim 2048
#define ENC  1024
#define DEC  1024
#define WTOT 2048
#define NEGV (-1e10f)

// ---------------- scratch ---------------------------------------------------
__device__ uint4 g_encH4[(size_t)Bdim * Sdim * ENC / 8]; // enc as fp16 [m][k]
__device__ uint4 g_weH4[DEC * ENC / 8];                  // w_e as fp16 [n][k]
__device__ float g_hpb[Bdim * DEC];                      // h_proj + bias
__device__ float g_part[(size_t)Bdim * Sdim * 8];        // per-(m, ntile) partials
__device__ float g_ctx_part[16 * Bdim * ENC];            // split-S ctx partials

// ---------------- helpers ----------------------------------------------------
__device__ __forceinline__ uint32_t smem_u32(const void* p) {
    uint32_t a;
    asm("{ .reg .u64 t; cvta.to.shared.u64 t, %1; cvt.u32.u64 %0, t; }"
        : "=r"(a) : "l"(p));
    return a;
}
__device__ __forceinline__ uint32_t h2pack(float x, float y) {
    __half2 h = __floats2half2_rn(x, y);
    return *(uint32_t*)&h;
}
__device__ __forceinline__ void mma_f16(float* d, uint32_t a0, uint32_t a1,
                                        uint32_t a2, uint32_t a3,
                                        uint32_t b0, uint32_t b1) {
    asm volatile(
        "mma.sync.aligned.m16n8k16.row.col.f32.f16.f16.f32 "
        "{%0,%1,%2,%3}, {%4,%5,%6,%7}, {%8,%9}, {%0,%1,%2,%3};"
        : "+f"(d[0]), "+f"(d[1]), "+f"(d[2]), "+f"(d[3])
        : "r"(a0), "r"(a1), "r"(a2), "r"(a3), "r"(b0), "r"(b1));
}
#define LDSM4(r0, r1, r2, r3, a) \
    asm volatile("ldmatrix.sync.aligned.m8n8.x4.shared.b16 {%0,%1,%2,%3}, [%4];" \
                 : "=r"(r0), "=r"(r1), "=r"(r2), "=r"(r3) : "r"(a))

// ---------------- enc fp32 -> fp16 ------------------------------------------
__global__ void enc_to_half(const float* __restrict__ enc) {
    size_t n8 = (size_t)Bdim * Sdim * ENC / 8;
    size_t stride = (size_t)gridDim.x * blockDim.x;
    for (size_t i = (size_t)blockIdx.x * blockDim.x + threadIdx.x; i < n8; i += stride) {
        float4 f0 = ((const float4*)enc)[2 * i];
        float4 f1 = ((const float4*)enc)[2 * i + 1];
        uint4 o;
        o.x = h2pack(f0.x, f0.y); o.y = h2pack(f0.z, f0.w);
        o.z = h2pack(f1.x, f1.y); o.w = h2pack(f1.z, f1.w);
        g_encH4[i] = o;
    }
}

// ---------------- h_proj + bias (8 k-rows per block) + w_e conversion -------
// grid 128 x 256 threads. Per block: stage w_h rows kb..kb+7 in smem (32KB),
// convert w_e rows kb..kb+7 to fp16, then thread (k,b) computes one dot.
// Hidden L2 traffic: 128 blocks x 128KB = 16MB (was 128MB).
__global__ __launch_bounds__(256) void hproj_kernel(
    const float* __restrict__ hidden,
    const float* __restrict__ attn_w,
    const float* __restrict__ attn_b) {
    __shared__ float ws8[8 * DEC];
    int tid = threadIdx.x;
    int kb = blockIdx.x * 8;

    // stage w_h rows (8 x 1024 floats) via float4
#pragma unroll
    for (int t = 0; t < 8; ++t) {
        int u = t * 256 + tid;                  // float4 units, 0..2047
        int r = u >> 8, c = u & 255;
        ((float4*)ws8)[r * 256 + c] =
            ((const float4*)(attn_w + (size_t)(kb + r) * WTOT))[c];
    }
    // convert w_e rows kb..kb+7 (8 x 128 uint4)
#pragma unroll
    for (int t = 0; t < 4; ++t) {
        int u = t * 256 + tid;                  // 0..1023
        int r = u >> 7, c = u & 127;
        const float* src = attn_w + (size_t)(kb + r) * WTOT + DEC + c * 8;
        float4 f0 = ((const float4*)src)[0];
        float4 f1 = ((const float4*)src)[1];
        uint4 o;
        o.x = h2pack(f0.x, f0.y); o.y = h2pack(f0.z, f0.w);
        o.z = h2pack(f1.x, f1.y); o.w = h2pack(f1.z, f1.w);
        g_weH4[(kb + r) * 128 + c] = o;
    }
    __syncthreads();

    int kk = tid >> 5;                          // 0..7
    int b  = tid & 31;
    const float* h = hidden + b * DEC;
    const float* w = ws8 + kk * DEC;
    float p = 0.f;
#pragma unroll 8
    for (int d = 0; d < DEC; d += 4) {
        p += h[d] * w[d] + h[d + 1] * w[d + 1]
           + h[d + 2] * w[d + 2] + h[d + 3] * w[d + 3];
    }
    g_hpb[b * DEC + kb + kk] = p + attn_b[kb + kk];
}

// ---------------- energy GEMM: fp16 mma.sync, frag-pipelined (R9 best) ------
#define NCHUNK 32
#define A_STG_B 10240            // 128 rows * 80B
#define B_STG_B 10240
#define STG_B   (A_STG_B + B_STG_B)
#define NSTAGE  5
#define DYN_SMEM (NSTAGE * STG_B)

__device__ __forceinline__ void issue_chunk(uint32_t sbase, int stage, int chunk,
                                            int m0, int n0, int tid) {
    uint32_t sb = sbase + stage * STG_B;
    int k0 = chunk * 32;
    const __half* encH = (const __half*)g_encH4;
    const __half* weH  = (const __half*)g_weH4;
#pragma unroll
    for (int t = 0; t < 8; ++t) {
        int u = t * 128 + tid;                  // 16B units: A 512, B 512
        const __half* g;
        uint32_t so;
        if (u < 512) {
            int r = u >> 2, seg = u & 3;
            so = (uint32_t)(r * 80 + seg * 16);
            g = encH + (size_t)(m0 + r) * ENC + k0 + seg * 8;
        } else {
            int v = u - 512;
            int r = v >> 2, seg = v & 3;
            so = (uint32_t)(A_STG_B + r * 80 + seg * 16);
            g = weH + (size_t)(n0 + r) * ENC + k0 + seg * 8;
        }
        asm volatile("cp.async.cg.shared.global [%0], [%1], 16;"
                     :: "r"(sb + so), "l"(g));
    }
    asm volatile("cp.async.commit_group;" ::: "memory");
}

struct Frag { uint32_t r[4]; };
struct FragSet { Frag a[4]; Frag b[4]; };

__device__ __forceinline__ void load_frags(FragSet& f, uint32_t sb,
                                           uint32_t aBase, uint32_t bBase,
                                           uint32_t koff) {
#pragma unroll
    for (int p = 0; p < 4; ++p)
        LDSM4(f.a[p].r[0], f.a[p].r[1], f.a[p].r[2], f.a[p].r[3],
              sb + aBase + p * 1280 + koff);
#pragma unroll
    for (int p = 0; p < 4; ++p)
        LDSM4(f.b[p].r[0], f.b[p].r[1], f.b[p].r[2], f.b[p].r[3],
              sb + bBase + p * 1280 + koff);
}

__device__ __forceinline__ void mma_set(float acc[4][8][4], const FragSet& f) {
#pragma unroll
    for (int mi = 0; mi < 4; ++mi)
#pragma unroll
        for (int p = 0; p < 4; ++p) {
            mma_f16(acc[mi][2 * p],     f.a[mi].r[0], f.a[mi].r[1],
                    f.a[mi].r[2], f.a[mi].r[3], f.b[p].r[0], f.b[p].r[1]);
            mma_f16(acc[mi][2 * p + 1], f.a[mi].r[0], f.a[mi].r[1],
                    f.a[mi].r[2], f.a[mi].r[3], f.b[p].r[2], f.b[p].r[3]);
        }
}

__global__ void __launch_bounds__(128, 2) energy_kernel(const float* __restrict__ v_w) {
    extern __shared__ uint32_t sm[];
    __shared__ float red[128][2];
    uint32_t sbase = smem_u32(sm);

    int tid = threadIdx.x;
    int wid = tid >> 5, lane = tid & 31;
    int wm = wid >> 1, wn = wid & 1;            // 2x2 warp grid
    int ty = lane >> 2, tx = lane & 3;
    int nt = blockIdx.x, mt = blockIdx.y;
    int m0 = mt * 128, n0 = nt * 128;
    int bb = m0 >> 11;

    int aRow = wm * 64 + (lane & 7) + (((lane >> 3) & 1) << 3);
    uint32_t aBase = (uint32_t)(aRow * 80 + ((lane >> 4) << 4));
    int bRow = wn * 64 + (lane & 7) + ((lane >> 4) << 3);
    uint32_t bBase = (uint32_t)(A_STG_B + bRow * 80 + (((lane >> 3) & 1) << 4));

    float acc[4][8][4];
#pragma unroll
    for (int mi = 0; mi < 4; ++mi)
#pragma unroll
        for (int ni = 0; ni < 8; ++ni)
#pragma unroll
            for (int c = 0; c < 4; ++c) acc[mi][ni][c] = 0.f;

    issue_chunk(sbase, 0, 0, m0, n0, tid);
    issue_chunk(sbase, 1, 1, m0, n0, tid);
    issue_chunk(sbase, 2, 2, m0, n0, tid);
    issue_chunk(sbase, 3, 3, m0, n0, tid);

    FragSet cur, nxt;
    asm volatile("cp.async.wait_group 3;" ::: "memory");
    __syncthreads();
    load_frags(cur, sbase, aBase, bBase, 0);

    for (int i = 0; i < NCHUNK; ++i) {
        if (i < 29)      asm volatile("cp.async.wait_group 2;" ::: "memory");
        else if (i == 29) asm volatile("cp.async.wait_group 1;" ::: "memory");
        else              asm volatile("cp.async.wait_group 0;" ::: "memory");
        __syncthreads();
        if (i + 4 < NCHUNK)
            issue_chunk(sbase, (i + 4) % NSTAGE, i + 4, m0, n0, tid);

        uint32_t sb  = sbase + (i % NSTAGE) * STG_B;
        uint32_t sbn = sbase + ((i + 1) % NSTAGE) * STG_B;

        load_frags(nxt, sb, aBase, bBase, 32);
        mma_set(acc, cur);
        if (i + 1 < NCHUNK) load_frags(cur, sbn, aBase, bBase, 0);
        mma_set(acc, nxt);
    }

    // Epilogue: tanh + v_w partial reduction over this block's 128 cols.
    int colbase = n0 + wn * 64 + tx * 2;
    int hb = bb * DEC;
    float pr[4][2];
#pragma unroll
    for (int mi = 0; mi < 4; ++mi) { pr[mi][0] = 0.f; pr[mi][1] = 0.f; }
#pragma unroll
    for (int ni = 0; ni < 8; ++ni) {
        int c0 = colbase + ni * 8;
        float hp0 = g_hpb[hb + c0],  hp1 = g_hpb[hb + c0 + 1];
        float vw0 = v_w[c0],         vw1 = v_w[c0 + 1];
#pragma unroll
        for (int mi = 0; mi < 4; ++mi) {
            pr[mi][0] += tanhf(acc[mi][ni][0] + hp0) * vw0
                       + tanhf(acc[mi][ni][1] + hp1) * vw1;
            pr[mi][1] += tanhf(acc[mi][ni][2] + hp0) * vw0
                       + tanhf(acc[mi][ni][3] + hp1) * vw1;
        }
    }
#pragma unroll
    for (int mi = 0; mi < 4; ++mi)
#pragma unroll
        for (int h = 0; h < 2; ++h) {
            float p = pr[mi][h];
            p += __shfl_xor_sync(0xffffffffu, p, 1);
            p += __shfl_xor_sync(0xffffffffu, p, 2);
            if (tx == 0) red[wm * 64 + mi * 16 + h * 8 + ty][wn] = p;
        }
    __syncthreads();
    g_part[((size_t)(m0 + tid)) * 8 + nt] = red[tid][0] + red[tid][1];
}

// ---------------- masked softmax (512 threads, sums 8 partials) -------------
__global__ void softmax_kernel(const int* __restrict__ mask, float* __restrict__ out) {
    int b = blockIdx.x;
    __shared__ float sh[Sdim];
    __shared__ float wr[16];
    int tid = threadIdx.x;  // 512

    float lmax = -1e30f;
    for (int s = tid; s < Sdim; s += 512) {
        float v;
        if (mask[b * Sdim + s] == 0) v = NEGV;
        else {
            const float4* pp = (const float4*)(g_part + ((size_t)(b * Sdim + s)) * 8);
            float4 p0 = pp[0], p1 = pp[1];
            v = ((p0.x + p0.y) + (p0.z + p0.w)) + ((p1.x + p1.y) + (p1.z + p1.w));
        }
        sh[s] = v;
        lmax = fmaxf(lmax, v);
    }
#pragma unroll
    for (int o = 16; o; o >>= 1) lmax = fmaxf(lmax, __shfl_xor_sync(~0u, lmax, o));
    if ((tid & 31) == 0) wr[tid >> 5] = lmax;
    __syncthreads();
    if (tid < 32) {
        float v = (tid < 16) ? wr[tid] : -1e30f;
#pragma unroll
        for (int o = 8; o; o >>= 1) v = fmaxf(v, __shfl_xor_sync(~0u, v, o));
        if (tid == 0) wr[0] = v;
    }
    __syncthreads();
    float gmax = wr[0];

    float lsum = 0.f;
    for (int s = tid; s < Sdim; s += 512) {
        float e = expf(sh[s] - gmax);
        sh[s] = e;
        lsum += e;
    }
    __syncthreads();
#pragma unroll
    for (int o = 16; o; o >>= 1) lsum += __shfl_xor_sync(~0u, lsum, o);
    if ((tid & 31) == 0) wr[tid >> 5] = lsum;
    __syncthreads();
    if (tid < 32) {
        float v = (tid < 16) ? wr[tid] : 0.f;
#pragma unroll
        for (int o = 8; o; o >>= 1) v += __shfl_xor_sync(~0u, v, o);
        if (tid == 0) wr[0] = v;
    }
    __syncthreads();
    float inv = 1.f / wr[0];
    float* w = out + Bdim * DEC;
    for (int s = tid; s < Sdim; s += 512) w[b * Sdim + s] = sh[s] * inv;
}

// ---------------- context (split-S x16, fp16 enc) ---------------------------
__global__ void ctx_part_kernel(const float* __restrict__ w) {
    const __half2* encH2 = (const __half2*)g_encH4;
    int e2 = blockIdx.x * 256 + threadIdx.x;    // half2 index, 0..511
    int b = blockIdx.y, z = blockIdx.z;
    const __half2* ep = encH2 + ((size_t)b * Sdim + z * 128) * (ENC / 2) + e2;
    const float* wp = w + b * Sdim + z * 128;
    float ax = 0.f, ay = 0.f;
    for (int s = 0; s < 128; s += 8) {
#pragma unroll
        for (int u = 0; u < 8; ++u) {
            float2 v = __half22float2(ep[(size_t)(s + u) * (ENC / 2)]);
            float wv = wp[s + u];
            ax += wv * v.x;
            ay += wv * v.y;
        }
    }
    float2* dst = (float2*)g_ctx_part;
    dst[((size_t)(z * Bdim + b) << 9) + e2] = make_float2(ax, ay);
}
__global__ void ctx_reduce_kernel(float* __restrict__ out) {
    int id = blockIdx.x * 256 + threadIdx.x;
    float s = 0.f;
#pragma unroll
    for (int z = 0; z < 16; ++z) s += g_ctx_part[(z << 15) + id];
    out[id] = s;
}

// ---------------------------------------------------------------------------
extern "C" void kernel_launch(void* const* d_in, const int* in_sizes, int n_in,
                              void* d_out, int out_size) {
    const float* hidden = (const float*)d_in[0];
    const float* enc    = (const float*)d_in[1];
    const int*   mask   = (const int*)d_in[2];
    const float* attn_w = (const float*)d_in[3];
    const float* attn_b = (const float*)d_in[4];
    const float* v_w    = (const float*)d_in[5];
    float* out = (float*)d_out;   // [context(32x1024), weights(32x2048)]

    cudaFuncSetAttribute(energy_kernel,
                         cudaFuncAttributeMaxDynamicSharedMemorySize, DYN_SMEM);

    enc_to_half<<<4096, 256>>>(enc);
    hproj_kernel<<<128, 256>>>(hidden, attn_w, attn_b);
    energy_kernel<<<dim3(8, 512), 128, DYN_SMEM>>>(v_w);
    softmax_kernel<<<Bdim, 512>>>(mask, out);
    ctx_part_kernel<<<dim3(2, Bdim, 16), 256>>>(out + Bdim * DEC);
    ctx_reduce_kernel<<<128, 256>>>(out);
}

// round 13
// speedup vs baseline: 1.2411x; 1.2411x over previous
#include <cuda_runtime.h>
#include <cuda_fp16.h>
#include <math.h>
#include <stdint.h>

#define Bdim 32
#define Sdim 2048
#define ENC  1024
#define DEC  1024
#define WTOT 2048
#define NEGV (-1e10f)

// ---------------- scratch ---------------------------------------------------
__device__ uint4 g_encH4[(size_t)Bdim * Sdim * ENC / 8]; // enc as fp16 [m][k]
__device__ uint4 g_weH4[DEC * ENC / 8];                  // w_e as fp16 [n][k]
__device__ float g_hpb[Bdim * DEC];                      // h_proj + bias
__device__ float g_part[(size_t)Bdim * Sdim * 8];        // per-(m, ntile) partials
__device__ float g_ctx_part[8 * Bdim * ENC];             // split-S ctx partials

// ---------------- helpers ----------------------------------------------------
__device__ __forceinline__ uint32_t smem_u32(const void* p) {
    uint32_t a;
    asm("{ .reg .u64 t; cvta.to.shared.u64 t, %1; cvt.u32.u64 %0, t; }"
        : "=r"(a) : "l"(p));
    return a;
}
__device__ __forceinline__ uint32_t h2pack(float x, float y) {
    __half2 h = __floats2half2_rn(x, y);
    return *(uint32_t*)&h;
}
__device__ __forceinline__ void mma_f16(float* d, uint32_t a0, uint32_t a1,
                                        uint32_t a2, uint32_t a3,
                                        uint32_t b0, uint32_t b1) {
    asm volatile(
        "mma.sync.aligned.m16n8k16.row.col.f32.f16.f16.f32 "
        "{%0,%1,%2,%3}, {%4,%5,%6,%7}, {%8,%9}, {%0,%1,%2,%3};"
        : "+f"(d[0]), "+f"(d[1]), "+f"(d[2]), "+f"(d[3])
        : "r"(a0), "r"(a1), "r"(a2), "r"(a3), "r"(b0), "r"(b1));
}
#define LDSM4(r0, r1, r2, r3, a) \
    asm volatile("ldmatrix.sync.aligned.m8n8.x4.shared.b16 {%0,%1,%2,%3}, [%4];" \
                 : "=r"(r0), "=r"(r1), "=r"(r2), "=r"(r3) : "r"(a))

// ---------------- enc fp32 -> fp16 ------------------------------------------
__global__ void enc_to_half(const float* __restrict__ enc) {
    size_t n8 = (size_t)Bdim * Sdim * ENC / 8;
    size_t stride = (size_t)gridDim.x * blockDim.x;
    for (size_t i = (size_t)blockIdx.x * blockDim.x + threadIdx.x; i < n8; i += stride) {
        float4 f0 = ((const float4*)enc)[2 * i];
        float4 f1 = ((const float4*)enc)[2 * i + 1];
        uint4 o;
        o.x = h2pack(f0.x, f0.y); o.y = h2pack(f0.z, f0.w);
        o.z = h2pack(f1.x, f1.y); o.w = h2pack(f1.z, f1.w);
        g_encH4[i] = o;
    }
}

// ---------------- h_proj + bias (8 k-rows/block, coalesced) + w_e conv ------
// grid 128 x 256 threads. Stage w_h rows kb..kb+7 in smem (32KB); thread
// (b = tid>>3, l = tid&7) streams hidden row b ONCE as float4 (8 consecutive
// lanes -> coalesced) and accumulates 8 per-k partials; shfl-reduce over l.
// Hidden L2 traffic: 128 blocks x 128KB = 16MB (R11: 128MB). w_e conversion
// for rows kb..kb+7 rides along.
__global__ __launch_bounds__(256) void hproj_kernel(
    const float* __restrict__ hidden,
    const float* __restrict__ attn_w,
    const float* __restrict__ attn_b) {
    __shared__ float ws8[8 * DEC];              // 32 KB
    int tid = threadIdx.x;
    int kb = blockIdx.x * 8;

    // stage w_h rows (8 x 1024 floats) via float4, coalesced
#pragma unroll
    for (int t = 0; t < 8; ++t) {
        int u = t * 256 + tid;                  // float4 units, 0..2047
        int r = u >> 8, c = u & 255;
        ((float4*)ws8)[r * 256 + c] =
            ((const float4*)(attn_w + (size_t)(kb + r) * WTOT))[c];
    }
    // convert w_e rows kb..kb+7 (8 x 128 uint4), coalesced
#pragma unroll
    for (int t = 0; t < 4; ++t) {
        int u = t * 256 + tid;                  // 0..1023
        int r = u >> 7, c = u & 127;
        const float* src = attn_w + (size_t)(kb + r) * WTOT + DEC + c * 8;
        float4 f0 = ((const float4*)src)[0];
        float4 f1 = ((const float4*)src)[1];
        uint4 o;
        o.x = h2pack(f0.x, f0.y); o.y = h2pack(f0.z, f0.w);
        o.z = h2pack(f1.x, f1.y); o.w = h2pack(f1.z, f1.w);
        g_weH4[(kb + r) * 128 + c] = o;
    }
    __syncthreads();

    int b = tid >> 3, l = tid & 7;
    const float4* h4 = (const float4*)(hidden + (size_t)b * DEC);
    const float4* w4 = (const float4*)ws8;
    float p[8];
#pragma unroll
    for (int kk = 0; kk < 8; ++kk) p[kk] = 0.f;

    for (int j = l; j < 256; j += 8) {          // float4 index within row
        float4 hv = h4[j];
#pragma unroll
        for (int kk = 0; kk < 8; ++kk) {
            float4 wv = w4[kk * 256 + j];       // LDS.128 broadcast over b-groups
            p[kk] += hv.x * wv.x + hv.y * wv.y + hv.z * wv.z + hv.w * wv.w;
        }
    }
#pragma unroll
    for (int kk = 0; kk < 8; ++kk) {
        p[kk] += __shfl_down_sync(0xffffffffu, p[kk], 4, 8);
        p[kk] += __shfl_down_sync(0xffffffffu, p[kk], 2, 8);
        p[kk] += __shfl_down_sync(0xffffffffu, p[kk], 1, 8);
    }
    if (l == 0) {
#pragma unroll
        for (int kk = 0; kk < 8; ++kk)
            g_hpb[b * DEC + kb + kk] = p[kk] + attn_b[kb + kk];
    }
}

// ---------------- energy GEMM: fp16 mma.sync, frag-pipelined (R9 best) ------
#define NCHUNK 32
#define A_STG_B 10240            // 128 rows * 80B
#define B_STG_B 10240
#define STG_B   (A_STG_B + B_STG_B)
#define NSTAGE  5
#define DYN_SMEM (NSTAGE * STG_B)

__device__ __forceinline__ void issue_chunk(uint32_t sbase, int stage, int chunk,
                                            int m0, int n0, int tid) {
    uint32_t sb = sbase + stage * STG_B;
    int k0 = chunk * 32;
    const __half* encH = (const __half*)g_encH4;
    const __half* weH  = (const __half*)g_weH4;
#pragma unroll
    for (int t = 0; t < 8; ++t) {
        int u = t * 128 + tid;                  // 16B units: A 512, B 512
        const __half* g;
        uint32_t so;
        if (u < 512) {
            int r = u >> 2, seg = u & 3;
            so = (uint32_t)(r * 80 + seg * 16);
            g = encH + (size_t)(m0 + r) * ENC + k0 + seg * 8;
        } else {
            int v = u - 512;
            int r = v >> 2, seg = v & 3;
            so = (uint32_t)(A_STG_B + r * 80 + seg * 16);
            g = weH + (size_t)(n0 + r) * ENC + k0 + seg * 8;
        }
        asm volatile("cp.async.cg.shared.global [%0], [%1], 16;"
                     :: "r"(sb + so), "l"(g));
    }
    asm volatile("cp.async.commit_group;" ::: "memory");
}

struct Frag { uint32_t r[4]; };
struct FragSet { Frag a[4]; Frag b[4]; };

__device__ __forceinline__ void load_frags(FragSet& f, uint32_t sb,
                                           uint32_t aBase, uint32_t bBase,
                                           uint32_t koff) {
#pragma unroll
    for (int p = 0; p < 4; ++p)
        LDSM4(f.a[p].r[0], f.a[p].r[1], f.a[p].r[2], f.a[p].r[3],
              sb + aBase + p * 1280 + koff);
#pragma unroll
    for (int p = 0; p < 4; ++p)
        LDSM4(f.b[p].r[0], f.b[p].r[1], f.b[p].r[2], f.b[p].r[3],
              sb + bBase + p * 1280 + koff);
}

__device__ __forceinline__ void mma_set(float acc[4][8][4], const FragSet& f) {
#pragma unroll
    for (int mi = 0; mi < 4; ++mi)
#pragma unroll
        for (int p = 0; p < 4; ++p) {
            mma_f16(acc[mi][2 * p],     f.a[mi].r[0], f.a[mi].r[1],
                    f.a[mi].r[2], f.a[mi].r[3], f.b[p].r[0], f.b[p].r[1]);
            mma_f16(acc[mi][2 * p + 1], f.a[mi].r[0], f.a[mi].r[1],
                    f.a[mi].r[2], f.a[mi].r[3], f.b[p].r[2], f.b[p].r[3]);
        }
}

__global__ void __launch_bounds__(128, 2) energy_kernel(const float* __restrict__ v_w) {
    extern __shared__ uint32_t sm[];
    __shared__ float red[128][2];
    uint32_t sbase = smem_u32(sm);

    int tid = threadIdx.x;
    int wid = tid >> 5, lane = tid & 31;
    int wm = wid >> 1, wn = wid & 1;            // 2x2 warp grid
    int ty = lane >> 2, tx = lane & 3;
    int nt = blockIdx.x, mt = blockIdx.y;
    int m0 = mt * 128, n0 = nt * 128;
    int bb = m0 >> 11;

    int aRow = wm * 64 + (lane & 7) + (((lane >> 3) & 1) << 3);
    uint32_t aBase = (uint32_t)(aRow * 80 + ((lane >> 4) << 4));
    int bRow = wn * 64 + (lane & 7) + ((lane >> 4) << 3);
    uint32_t bBase = (uint32_t)(A_STG_B + bRow * 80 + (((lane >> 3) & 1) << 4));

    float acc[4][8][4];
#pragma unroll
    for (int mi = 0; mi < 4; ++mi)
#pragma unroll
        for (int ni = 0; ni < 8; ++ni)
#pragma unroll
            for (int c = 0; c < 4; ++c) acc[mi][ni][c] = 0.f;

    issue_chunk(sbase, 0, 0, m0, n0, tid);
    issue_chunk(sbase, 1, 1, m0, n0, tid);
    issue_chunk(sbase, 2, 2, m0, n0, tid);
    issue_chunk(sbase, 3, 3, m0, n0, tid);

    FragSet cur, nxt;
    asm volatile("cp.async.wait_group 3;" ::: "memory");
    __syncthreads();
    load_frags(cur, sbase, aBase, bBase, 0);

    for (int i = 0; i < NCHUNK; ++i) {
        if (i < 29)      asm volatile("cp.async.wait_group 2;" ::: "memory");
        else if (i == 29) asm volatile("cp.async.wait_group 1;" ::: "memory");
        else              asm volatile("cp.async.wait_group 0;" ::: "memory");
        __syncthreads();
        if (i + 4 < NCHUNK)
            issue_chunk(sbase, (i + 4) % NSTAGE, i + 4, m0, n0, tid);

        uint32_t sb  = sbase + (i % NSTAGE) * STG_B;
        uint32_t sbn = sbase + ((i + 1) % NSTAGE) * STG_B;

        load_frags(nxt, sb, aBase, bBase, 32);
        mma_set(acc, cur);
        if (i + 1 < NCHUNK) load_frags(cur, sbn, aBase, bBase, 0);
        mma_set(acc, nxt);
    }

    // Epilogue: tanh + v_w partial reduction over this block's 128 cols.
    int colbase = n0 + wn * 64 + tx * 2;
    int hb = bb * DEC;
    float pr[4][2];
#pragma unroll
    for (int mi = 0; mi < 4; ++mi) { pr[mi][0] = 0.f; pr[mi][1] = 0.f; }
#pragma unroll
    for (int ni = 0; ni < 8; ++ni) {
        int c0 = colbase + ni * 8;
        float hp0 = g_hpb[hb + c0],  hp1 = g_hpb[hb + c0 + 1];
        float vw0 = v_w[c0],         vw1 = v_w[c0 + 1];
#pragma unroll
        for (int mi = 0; mi < 4; ++mi) {
            pr[mi][0] += tanhf(acc[mi][ni][0] + hp0) * vw0
                       + tanhf(acc[mi][ni][1] + hp1) * vw1;
            pr[mi][1] += tanhf(acc[mi][ni][2] + hp0) * vw0
                       + tanhf(acc[mi][ni][3] + hp1) * vw1;
        }
    }
#pragma unroll
    for (int mi = 0; mi < 4; ++mi)
#pragma unroll
        for (int h = 0; h < 2; ++h) {
            float p = pr[mi][h];
            p += __shfl_xor_sync(0xffffffffu, p, 1);
            p += __shfl_xor_sync(0xffffffffu, p, 2);
            if (tx == 0) red[wm * 64 + mi * 16 + h * 8 + ty][wn] = p;
        }
    __syncthreads();
    g_part[((size_t)(m0 + tid)) * 8 + nt] = red[tid][0] + red[tid][1];
}

// ---------------- masked softmax (512 threads, sums 8 partials) -------------
__global__ void softmax_kernel(const int* __restrict__ mask, float* __restrict__ out) {
    int b = blockIdx.x;
    __shared__ float sh[Sdim];
    __shared__ float wr[16];
    int tid = threadIdx.x;  // 512

    float lmax = -1e30f;
    for (int s = tid; s < Sdim; s += 512) {
        float v;
        if (mask[b * Sdim + s] == 0) v = NEGV;
        else {
            const float4* pp = (const float4*)(g_part + ((size_t)(b * Sdim + s)) * 8);
            float4 p0 = pp[0], p1 = pp[1];
            v = ((p0.x + p0.y) + (p0.z + p0.w)) + ((p1.x + p1.y) + (p1.z + p1.w));
        }
        sh[s] = v;
        lmax = fmaxf(lmax, v);
    }
#pragma unroll
    for (int o = 16; o; o >>= 1) lmax = fmaxf(lmax, __shfl_xor_sync(~0u, lmax, o));
    if ((tid & 31) == 0) wr[tid >> 5] = lmax;
    __syncthreads();
    if (tid < 32) {
        float v = (tid < 16) ? wr[tid] : -1e30f;
#pragma unroll
        for (int o = 8; o; o >>= 1) v = fmaxf(v, __shfl_xor_sync(~0u, v, o));
        if (tid == 0) wr[0] = v;
    }
    __syncthreads();
    float gmax = wr[0];

    float lsum = 0.f;
    for (int s = tid; s < Sdim; s += 512) {
        float e = expf(sh[s] - gmax);
        sh[s] = e;
        lsum += e;
    }
    __syncthreads();
#pragma unroll
    for (int o = 16; o; o >>= 1) lsum += __shfl_xor_sync(~0u, lsum, o);
    if ((tid & 31) == 0) wr[tid >> 5] = lsum;
    __syncthreads();
    if (tid < 32) {
        float v = (tid < 16) ? wr[tid] : 0.f;
#pragma unroll
        for (int o = 8; o; o >>= 1) v += __shfl_xor_sync(~0u, v, o);
        if (tid == 0) wr[0] = v;
    }
    __syncthreads();
    float inv = 1.f / wr[0];
    float* w = out + Bdim * DEC;
    for (int s = tid; s < Sdim; s += 512) w[b * Sdim + s] = sh[s] * inv;
}

// ---------------- context (split-S x8, fp16 enc) ----------------------------
__global__ void ctx_part_kernel(const float* __restrict__ w) {
    const __half2* encH2 = (const __half2*)g_encH4;
    int e2 = blockIdx.x * 256 + threadIdx.x;    // half2 index, 0..511
    int b = blockIdx.y, z = blockIdx.z;
    const __half2* ep = encH2 + ((size_t)b * Sdim + z * 256) * (ENC / 2) + e2;
    const float* wp = w + b * Sdim + z * 256;
    float ax = 0.f, ay = 0.f;
    for (int s = 0; s < 256; s += 8) {
#pragma unroll
        for (int u = 0; u < 8; ++u) {
            float2 v = __half22float2(ep[(size_t)(s + u) * (ENC / 2)]);
            float wv = wp[s + u];
            ax += wv * v.x;
            ay += wv * v.y;
        }
    }
    float2* dst = (float2*)g_ctx_part;
    dst[((size_t)(z * Bdim + b) << 9) + e2] = make_float2(ax, ay);
}
__global__ void ctx_reduce_kernel(float* __restrict__ out) {
    int id = blockIdx.x * 256 + threadIdx.x;
    float s = 0.f;
#pragma unroll
    for (int z = 0; z < 8; ++z) s += g_ctx_part[(z << 15) + id];
    out[id] = s;
}

// ---------------------------------------------------------------------------
extern "C" void kernel_launch(void* const* d_in, const int* in_sizes, int n_in,
                              void* d_out, int out_size) {
    const float* hidden = (const float*)d_in[0];
    const float* enc    = (const float*)d_in[1];
    const int*   mask   = (const int*)d_in[2];
    const float* attn_w = (const float*)d_in[3];
    const float* attn_b = (const float*)d_in[4];
    const float* v_w    = (const float*)d_in[5];
    float* out = (float*)d_out;   // [context(32x1024), weights(32x2048)]

    cudaFuncSetAttribute(energy_kernel,
                         cudaFuncAttributeMaxDynamicSharedMemorySize, DYN_SMEM);

    enc_to_half<<<4096, 256>>>(enc);
    hproj_kernel<<<128, 256>>>(hidden, attn_w, attn_b);
    energy_kernel<<<dim3(8, 512), 128, DYN_SMEM>>>(v_w);
    softmax_kernel<<<Bdim, 512>>>(mask, out);
    ctx_part_kernel<<<dim3(2, Bdim, 8), 256>>>(out + Bdim * DEC);
    ctx_reduce_kernel<<<128, 256>>>(out);
}